// round 5
// baseline (speedup 1.0000x reference)
#include <cuda_runtime.h>
#include <cuda_bf16.h>
#include <cstdint>

#define N_NODES 100000
#define N_EDGES 600000
#define N_FEAT  128
#define NBLK    ((N_NODES + 127) / 128)   // 782

// Scratch (device globals — no allocation allowed)
__device__ float g_dinv[N_NODES];
__device__ int g_cnt[N_NODES];          // histogram, then bucket cursor
__device__ int g_off[N_NODES + 1];      // CSR offsets (by dst)
__device__ int g_esrc[N_EDGES];         // src ids, bucketed by dst
__device__ unsigned int g_or;           // dtype detection
// W split into bf16 hi/lo, pre-swizzled into m16n8k16 B-fragment order
__device__ __align__(16) uint2 g_wfragH[128 * 8 * 4];
__device__ __align__(16) uint2 g_wfragL[128 * 8 * 4];

// ---------------- dtype detection (sampled, one block) ----------------
__global__ void k_detect(const unsigned int* __restrict__ w) {
    __shared__ unsigned int s_or;
    if (threadIdx.x == 0) s_or = 0u;
    __syncthreads();
    unsigned int v = 0u;
#pragma unroll
    for (int k = 0; k < 16; k++) {
        int i = (threadIdx.x * 16 + k) * 146;   // <= 597,870 < N_EDGES
        v |= w[2 * i + 1];                      // odd word: int64 hi-word if i64
    }
#pragma unroll
    for (int s = 16; s > 0; s >>= 1) v |= __shfl_xor_sync(0xffffffffu, v, s);
    if ((threadIdx.x & 31) == 0 && v) atomicOr(&s_or, v);
    __syncthreads();
    if (threadIdx.x == 0) g_or = s_or;          // 0 => int64 layout
}

__global__ void k_zero_cnt() {
    int i = blockIdx.x * blockDim.x + threadIdx.x;
    if (i < N_NODES) g_cnt[i] = 0;
}

__device__ __forceinline__ int dec_clamp(int v) {
    return min(max(v, 0), N_NODES - 1);
}

// ---------------- histogram over dst ----------------
__global__ void k_hist(const int* __restrict__ w) {
    int i = blockIdx.x * blockDim.x + threadIdx.x;
    if (i >= N_EDGES) return;
    int d = (g_or == 0u) ? w[2 * (N_EDGES + i)] : w[N_EDGES + i];
    atomicAdd(&g_cnt[dec_clamp(d)], 1);
}

// ---------------- scan: offsets + cursor reset + dinv ----------------
__global__ void __launch_bounds__(1024) k_scan() {
    __shared__ int ssum[1024];
    const int CHUNK = 98;   // 98*1024 >= 100000
    int t = threadIdx.x;
    int begin = t * CHUNK;
    int end = min(begin + CHUNK, N_NODES);
    int s = 0;
    for (int i = begin; i < end; i++) s += g_cnt[i];
    ssum[t] = s;
    __syncthreads();
    for (int d = 1; d < 1024; d <<= 1) {
        int v = (t >= d) ? ssum[t - d] : 0;
        __syncthreads();
        ssum[t] += v;
        __syncthreads();
    }
    int run = (t > 0) ? ssum[t - 1] : 0;
    for (int i = begin; i < end; i++) {
        int c = g_cnt[i];
        g_off[i] = run;
        g_cnt[i] = run;                         // becomes bucket cursor
        g_dinv[i] = rsqrtf((float)(c + 1));     // +1 self-loop
        run += c;
    }
    if (t == 1023) g_off[N_NODES] = run;
}

// ---------------- bucket: esrc grouped by dst ----------------
__global__ void k_bucket(const int* __restrict__ w) {
    int i = blockIdx.x * blockDim.x + threadIdx.x;
    if (i >= N_EDGES) return;
    int s, d;
    if (g_or == 0u) { s = w[2 * i]; d = w[2 * (N_EDGES + i)]; }
    else            { s = w[i];     d = w[N_EDGES + i]; }
    s = dec_clamp(s); d = dec_clamp(d);
    int slot = atomicAdd(&g_cnt[d], 1);
    g_esrc[slot] = s;
}

// ---------------- W split prep: fp32 -> bf16 hi/lo, fragment-order -------
__global__ void k_wsplit(const float* __restrict__ W) {
    int i = blockIdx.x * blockDim.x + threadIdx.x;   // 16384
    if (i >= 128 * 128) return;
    int k = i >> 7, n = i & 127;                     // W[k][n]
    float v = W[i];
    __nv_bfloat16 h = __float2bfloat16_rn(v);
    __nv_bfloat16 l = __float2bfloat16_rn(v - __bfloat162float(h));
    int kstep = k >> 4, kk = k & 15;
    int t = (kk & 7) >> 1;
    int idx4 = (kk < 8) ? (kk & 1) : (2 + (kk & 1));
    int base = (n * 8 + kstep) * 4 + t;
    ((__nv_bfloat16*)g_wfragH)[base * 4 + idx4] = h;
    ((__nv_bfloat16*)g_wfragL)[base * 4 + idx4] = l;
}

// ---------------- fused: CSR aggregate + bf16x3 MMA + bias/relu ----------
#define MMA_BF16(d, a0, a1, a2, a3, b0, b1)                                 \
    asm volatile(                                                           \
        "mma.sync.aligned.m16n8k16.row.col.f32.bf16.bf16.f32 "              \
        "{%0,%1,%2,%3}, {%4,%5,%6,%7}, {%8,%9}, {%0,%1,%2,%3};"             \
        : "+f"(d[0]), "+f"(d[1]), "+f"(d[2]), "+f"(d[3])                    \
        : "r"(a0), "r"(a1), "r"(a2), "r"(a3), "r"(b0), "r"(b1))

// smem: WfH [0,32768) | Ah [32768,+33792) | Al (+33792)
#define SM_WFH 0
#define SM_AH  32768
#define SM_AL  (32768 + 33792)
#define SM_TOTAL (32768 + 2 * 33792)   // 100,352 B -> 2 blocks/SM

__global__ void __launch_bounds__(256, 2)
k_gemm_fused(const float4* __restrict__ x4, const float* __restrict__ b,
             float* __restrict__ out) {
    extern __shared__ char sm[];
    uint2* WfH = (uint2*)(sm + SM_WFH);
    __nv_bfloat16* Ah = (__nv_bfloat16*)(sm + SM_AH);  // [128][132]
    __nv_bfloat16* Al = (__nv_bfloat16*)(sm + SM_AL);

    int tid = threadIdx.x;
    int warp = tid >> 5, lane = tid & 31;
    int rowbase = blockIdx.x * 128;

    // stage WfH (4096 uint2)
#pragma unroll
    for (int i = 0; i < 16; i++) WfH[tid + i * 256] = g_wfragH[tid + i * 256];

    // ---- phase 1: aggregate 16 rows per warp, registers -> smem bf16 ----
    for (int rr = 0; rr < 16; rr++) {
        int node = min(rowbase + warp * 16 + rr, N_NODES - 1);
        float din = g_dinv[node];
        float s2 = din * din;
        float4 acc = x4[(size_t)node * 32 + lane];
        acc.x *= s2; acc.y *= s2; acc.z *= s2; acc.w *= s2;

        int e = g_off[node], end = g_off[node + 1];
        while (e < end) {
            int m = end - e; if (m > 32) m = 32;
            int   sl = (lane < m) ? g_esrc[e + lane] : 0;
            float dl = (lane < m) ? g_dinv[sl] * din : 0.0f;
            int j = 0;
            for (; j + 4 <= m; j += 4) {
                int s0 = __shfl_sync(0xffffffffu, sl, j + 0);
                int s1 = __shfl_sync(0xffffffffu, sl, j + 1);
                int s2i = __shfl_sync(0xffffffffu, sl, j + 2);
                int s3 = __shfl_sync(0xffffffffu, sl, j + 3);
                float n0 = __shfl_sync(0xffffffffu, dl, j + 0);
                float n1 = __shfl_sync(0xffffffffu, dl, j + 1);
                float n2 = __shfl_sync(0xffffffffu, dl, j + 2);
                float n3 = __shfl_sync(0xffffffffu, dl, j + 3);
                float4 v0 = x4[(size_t)s0 * 32 + lane];
                float4 v1 = x4[(size_t)s1 * 32 + lane];
                float4 v2 = x4[(size_t)s2i * 32 + lane];
                float4 v3 = x4[(size_t)s3 * 32 + lane];
                acc.x += v0.x * n0 + v1.x * n1 + v2.x * n2 + v3.x * n3;
                acc.y += v0.y * n0 + v1.y * n1 + v2.y * n2 + v3.y * n3;
                acc.z += v0.z * n0 + v1.z * n1 + v2.z * n2 + v3.z * n3;
                acc.w += v0.w * n0 + v1.w * n1 + v2.w * n2 + v3.w * n3;
            }
            for (; j < m; j++) {
                int s0 = __shfl_sync(0xffffffffu, sl, j);
                float n0 = __shfl_sync(0xffffffffu, dl, j);
                float4 v0 = x4[(size_t)s0 * 32 + lane];
                acc.x += v0.x * n0; acc.y += v0.y * n0;
                acc.z += v0.z * n0; acc.w += v0.w * n0;
            }
            e += m;
        }

        int r = warp * 16 + rr;
        float vals[4] = {acc.x, acc.y, acc.z, acc.w};
#pragma unroll
        for (int jj = 0; jj < 4; jj++) {
            __nv_bfloat16 h = __float2bfloat16_rn(vals[jj]);
            Ah[r * 132 + lane * 4 + jj] = h;
            Al[r * 132 + lane * 4 + jj] =
                __float2bfloat16_rn(vals[jj] - __bfloat162float(h));
        }
    }
    __syncthreads();

    // ---- phase 2: bf16x3 MMA ----
    int g = lane >> 2, t = lane & 3;
    int r0 = warp * 16 + g, r1 = r0 + 8;

    float acc[16][4];
#pragma unroll
    for (int nt = 0; nt < 16; nt++)
#pragma unroll
        for (int j = 0; j < 4; j++) acc[nt][j] = 0.0f;

#pragma unroll
    for (int ks = 0; ks < 8; ks++) {
        int k0 = ks * 16;
        uint32_t ah0 = *(const uint32_t*)&Ah[r0 * 132 + k0 + 2 * t];
        uint32_t ah1 = *(const uint32_t*)&Ah[r1 * 132 + k0 + 2 * t];
        uint32_t ah2 = *(const uint32_t*)&Ah[r0 * 132 + k0 + 2 * t + 8];
        uint32_t ah3 = *(const uint32_t*)&Ah[r1 * 132 + k0 + 2 * t + 8];
        uint32_t al0 = *(const uint32_t*)&Al[r0 * 132 + k0 + 2 * t];
        uint32_t al1 = *(const uint32_t*)&Al[r1 * 132 + k0 + 2 * t];
        uint32_t al2 = *(const uint32_t*)&Al[r0 * 132 + k0 + 2 * t + 8];
        uint32_t al3 = *(const uint32_t*)&Al[r1 * 132 + k0 + 2 * t + 8];
#pragma unroll
        for (int nt = 0; nt < 16; nt++) {
            int n = nt * 8 + g;
            uint2 bh = WfH[(n * 8 + ks) * 4 + t];
            uint2 bl = g_wfragL[(n * 8 + ks) * 4 + t];  // L1-resident
            MMA_BF16(acc[nt], ah0, ah1, ah2, ah3, bh.x, bh.y);
            MMA_BF16(acc[nt], ah0, ah1, ah2, ah3, bl.x, bl.y);
            MMA_BF16(acc[nt], al0, al1, al2, al3, bh.x, bh.y);
        }
    }

    // epilogue: bias + relu, guarded stores
    int growA = rowbase + warp * 16 + g;
#pragma unroll
    for (int nt = 0; nt < 16; nt++) {
        int c = nt * 8 + 2 * t;
        float2 bb = *(const float2*)&b[c];
        if (growA < N_NODES) {
            float2 o;
            o.x = fmaxf(acc[nt][0] + bb.x, 0.0f);
            o.y = fmaxf(acc[nt][1] + bb.y, 0.0f);
            *(float2*)&out[(size_t)growA * 128 + c] = o;
        }
        int grow1 = growA + 8;
        if (grow1 < N_NODES) {
            float2 o;
            o.x = fmaxf(acc[nt][2] + bb.x, 0.0f);
            o.y = fmaxf(acc[nt][3] + bb.y, 0.0f);
            *(float2*)&out[(size_t)grow1 * 128 + c] = o;
        }
    }
}

extern "C" void kernel_launch(void* const* d_in, const int* in_sizes, int n_in,
                              void* d_out, int out_size) {
    const float* x  = nullptr;
    const float* W  = nullptr;
    const float* b  = nullptr;
    const void*  ei = nullptr;
    for (int i = 0; i < n_in; i++) {
        switch (in_sizes[i]) {
            case 12800000: x  = (const float*)d_in[i]; break;
            case 16384:    W  = (const float*)d_in[i]; break;
            case 128:      b  = (const float*)d_in[i]; break;
            case 1200000:  ei = d_in[i];               break;
            default: break;
        }
    }
    float* out = (float*)d_out;
    (void)out_size;
    if (!x || !W || !b || !ei) return;

    k_detect  <<<1, 256>>>((const unsigned int*)ei);
    k_zero_cnt<<<(N_NODES + 255) / 256, 256>>>();
    k_wsplit  <<<(128 * 128 + 255) / 256, 256>>>(W);
    k_hist    <<<(N_EDGES + 255) / 256, 256>>>((const int*)ei);
    k_scan    <<<1, 1024>>>();
    k_bucket  <<<(N_EDGES + 255) / 256, 256>>>((const int*)ei);

    cudaFuncSetAttribute(k_gemm_fused,
                         cudaFuncAttributeMaxDynamicSharedMemorySize, SM_TOTAL);
    k_gemm_fused<<<NBLK, 256, SM_TOTAL>>>((const float4*)x, b, out);
}

// round 6
// speedup vs baseline: 1.9151x; 1.9151x over previous
#include <cuda_runtime.h>
#include <cuda_bf16.h>
#include <cstdint>

#define N_NODES 100000
#define N_EDGES 600000
#define N_FEAT  128
#define NBLK    ((N_NODES + 127) / 128)   // 782

// Scratch (device globals). 16B alignment load-bearing for red.v4.
__device__ __align__(16) float g_deg[N_NODES];
__device__ __align__(16) float g_dinv[N_NODES];
__device__ __align__(16) float g_aggx[(size_t)N_NODES * N_FEAT];
__device__ int g_src[N_EDGES];
__device__ int g_dst[N_EDGES];
__device__ unsigned int g_or;   // dtype detection (0 => int64 layout)
// W split into bf16 hi/lo, m16n8k16 B-fragment order
__device__ __align__(16) uint2 g_wfragH[128 * 8 * 4];
__device__ __align__(16) uint2 g_wfragL[128 * 8 * 4];

// ---------------- prep: deg init + W split + dtype detect (one launch) ----
#define DEG_BLKS ((N_NODES + 255) / 256)          // 391
#define WSP_BLKS ((128 * 128 + 255) / 256)        // 64

__global__ void k_prep(const float* __restrict__ W,
                       const unsigned int* __restrict__ ew) {
    int bid = blockIdx.x, tid = threadIdx.x;
    if (bid < DEG_BLKS) {
        int i = bid * 256 + tid;
        if (i < N_NODES) g_deg[i] = 1.0f;          // self-loop pre-counted
        if (bid == 0) {
            // dtype detect: sample 4096 odd words across the buffer
            __shared__ unsigned int s_or;
            if (tid == 0) s_or = 0u;
            __syncthreads();
            unsigned int v = 0u;
#pragma unroll
            for (int k = 0; k < 16; k++) {
                int e = (tid * 16 + k) * 146;      // <= 597,870 < N_EDGES
                v |= ew[2 * e + 1];
            }
#pragma unroll
            for (int s = 16; s > 0; s >>= 1)
                v |= __shfl_xor_sync(0xffffffffu, v, s);
            if ((tid & 31) == 0 && v) atomicOr(&s_or, v);
            __syncthreads();
            if (tid == 0) g_or = s_or;
        }
    } else {
        int i = (bid - DEG_BLKS) * 256 + tid;      // W split
        if (i < 128 * 128) {
            int k = i >> 7, n = i & 127;
            float v = W[i];
            __nv_bfloat16 h = __float2bfloat16_rn(v);
            __nv_bfloat16 l = __float2bfloat16_rn(v - __bfloat162float(h));
            int kstep = k >> 4, kk = k & 15;
            int t = (kk & 7) >> 1;
            int idx4 = (kk < 8) ? (kk & 1) : (2 + (kk & 1));
            int base = (n * 8 + kstep) * 4 + t;
            ((__nv_bfloat16*)g_wfragH)[base * 4 + idx4] = h;
            ((__nv_bfloat16*)g_wfragL)[base * 4 + idx4] = l;
        }
    }
}

// ---------------- decode + degree scatter ----------------
__global__ void k_decode_deg(const int* __restrict__ w) {
    int i = blockIdx.x * blockDim.x + threadIdx.x;
    if (i >= N_EDGES) return;
    int s, d;
    if (g_or == 0u) { s = w[2 * i]; d = w[2 * (N_EDGES + i)]; }
    else            { s = w[i];     d = w[N_EDGES + i]; }
    s = min(max(s, 0), N_NODES - 1);
    d = min(max(d, 0), N_NODES - 1);
    g_src[i] = s;
    g_dst[i] = d;
    atomicAdd(&g_deg[d], 1.0f);
}

// ---------------- init aggx = x * dinv^2, also writes g_dinv ----------------
__global__ void k_init_aggx_dinv(const float4* __restrict__ x4) {
    int t = blockIdx.x * blockDim.x + threadIdx.x;  // N*32 threads
    if (t < N_NODES * 32) {
        int node = t >> 5;
        float di = rsqrtf(g_deg[node]);             // deg >= 1 always
        if ((t & 31) == 0) g_dinv[node] = di;
        float s = di * di;
        float4 v = x4[t];
        v.x *= s; v.y *= s; v.z *= s; v.w *= s;
        ((float4*)g_aggx)[t] = v;
    }
}

// ---------------- edge scatter: aggx[dst] += x[src] * norm ----------------
__global__ void k_edge_scatter(const float4* __restrict__ x4) {
    int t = blockIdx.x * blockDim.x + threadIdx.x;
    int e = t >> 5;
    if (e >= N_EDGES) return;
    int lane = t & 31;
    int s = g_src[e];
    int d = g_dst[e];
    float norm = g_dinv[s] * g_dinv[d];
    float4 v = x4[s * 32 + lane];
    v.x *= norm; v.y *= norm; v.z *= norm; v.w *= norm;
    float* p = &g_aggx[(size_t)d * N_FEAT + lane * 4];
    asm volatile("red.global.add.v4.f32 [%0], {%1, %2, %3, %4};"
                 :: "l"(p), "f"(v.x), "f"(v.y), "f"(v.z), "f"(v.w)
                 : "memory");
}

// ---------------- GEMM: out = relu(aggx @ W + b) via bf16x3 mma ----------
#define MMA_BF16(d, a0, a1, a2, a3, b0, b1)                                 \
    asm volatile(                                                           \
        "mma.sync.aligned.m16n8k16.row.col.f32.bf16.bf16.f32 "              \
        "{%0,%1,%2,%3}, {%4,%5,%6,%7}, {%8,%9}, {%0,%1,%2,%3};"             \
        : "+f"(d[0]), "+f"(d[1]), "+f"(d[2]), "+f"(d[3])                    \
        : "r"(a0), "r"(a1), "r"(a2), "r"(a3), "r"(b0), "r"(b1))

#define SM_WFH 0
#define SM_WFL 32768
#define SM_AH  65536
#define SM_AL  (65536 + 33792)
#define SM_TOTAL (65536 + 2 * 33792)   // 133,120 B

__global__ void __launch_bounds__(256, 1)
k_gemm_relu(const float* __restrict__ b, float* __restrict__ out) {
    extern __shared__ char sm[];
    uint2* WfH = (uint2*)(sm + SM_WFH);
    uint2* WfL = (uint2*)(sm + SM_WFL);
    __nv_bfloat16* Ah = (__nv_bfloat16*)(sm + SM_AH);  // [128][132]
    __nv_bfloat16* Al = (__nv_bfloat16*)(sm + SM_AL);

    int tid = threadIdx.x;

#pragma unroll
    for (int i = 0; i < 16; i++) {
        WfH[tid + i * 256] = g_wfragH[tid + i * 256];
        WfL[tid + i * 256] = g_wfragL[tid + i * 256];
    }

    int rowbase = blockIdx.x * 128;
    const float4* A4 = (const float4*)g_aggx;
#pragma unroll
    for (int i = 0; i < 16; i++) {
        int idx = tid + i * 256;
        int r   = idx >> 5;
        int c4  = (idx & 31) * 4;
        int grow = min(rowbase + r, N_NODES - 1);
        float4 v = A4[(size_t)grow * 32 + (idx & 31)];
        float vs[4] = {v.x, v.y, v.z, v.w};
#pragma unroll
        for (int j = 0; j < 4; j++) {
            __nv_bfloat16 h = __float2bfloat16_rn(vs[j]);
            Ah[r * 132 + c4 + j] = h;
            Al[r * 132 + c4 + j] = __float2bfloat16_rn(vs[j] - __bfloat162float(h));
        }
    }
    __syncthreads();

    int warp = tid >> 5, lane = tid & 31;
    int g = lane >> 2, t = lane & 3;
    int r0 = warp * 16 + g, r1 = r0 + 8;

    float acc[16][4];
#pragma unroll
    for (int nt = 0; nt < 16; nt++)
#pragma unroll
        for (int j = 0; j < 4; j++) acc[nt][j] = 0.0f;

#pragma unroll
    for (int ks = 0; ks < 8; ks++) {
        int k0 = ks * 16;
        uint32_t ah0 = *(const uint32_t*)&Ah[r0 * 132 + k0 + 2 * t];
        uint32_t ah1 = *(const uint32_t*)&Ah[r1 * 132 + k0 + 2 * t];
        uint32_t ah2 = *(const uint32_t*)&Ah[r0 * 132 + k0 + 2 * t + 8];
        uint32_t ah3 = *(const uint32_t*)&Ah[r1 * 132 + k0 + 2 * t + 8];
        uint32_t al0 = *(const uint32_t*)&Al[r0 * 132 + k0 + 2 * t];
        uint32_t al1 = *(const uint32_t*)&Al[r1 * 132 + k0 + 2 * t];
        uint32_t al2 = *(const uint32_t*)&Al[r0 * 132 + k0 + 2 * t + 8];
        uint32_t al3 = *(const uint32_t*)&Al[r1 * 132 + k0 + 2 * t + 8];
#pragma unroll
        for (int nt = 0; nt < 16; nt++) {
            int n = nt * 8 + g;
            uint2 bh = WfH[(n * 8 + ks) * 4 + t];
            uint2 bl = WfL[(n * 8 + ks) * 4 + t];
            MMA_BF16(acc[nt], ah0, ah1, ah2, ah3, bh.x, bh.y);
            MMA_BF16(acc[nt], ah0, ah1, ah2, ah3, bl.x, bl.y);
            MMA_BF16(acc[nt], al0, al1, al2, al3, bh.x, bh.y);
        }
    }

    int growA = rowbase + warp * 16 + g;
#pragma unroll
    for (int nt = 0; nt < 16; nt++) {
        int c = nt * 8 + 2 * t;
        float2 bb = *(const float2*)&b[c];
        if (growA < N_NODES) {
            float2 o;
            o.x = fmaxf(acc[nt][0] + bb.x, 0.0f);
            o.y = fmaxf(acc[nt][1] + bb.y, 0.0f);
            *(float2*)&out[(size_t)growA * 128 + c] = o;
        }
        int grow1 = growA + 8;
        if (grow1 < N_NODES) {
            float2 o;
            o.x = fmaxf(acc[nt][2] + bb.x, 0.0f);
            o.y = fmaxf(acc[nt][3] + bb.y, 0.0f);
            *(float2*)&out[(size_t)grow1 * 128 + c] = o;
        }
    }
}

extern "C" void kernel_launch(void* const* d_in, const int* in_sizes, int n_in,
                              void* d_out, int out_size) {
    const float* x  = nullptr;
    const float* W  = nullptr;
    const float* b  = nullptr;
    const void*  ei = nullptr;
    for (int i = 0; i < n_in; i++) {
        switch (in_sizes[i]) {
            case 12800000: x  = (const float*)d_in[i]; break;
            case 16384:    W  = (const float*)d_in[i]; break;
            case 128:      b  = (const float*)d_in[i]; break;
            case 1200000:  ei = d_in[i];               break;
            default: break;
        }
    }
    float* out = (float*)d_out;
    (void)out_size;
    if (!x || !W || !b || !ei) return;

    // launch 0: deg init + W split + dtype detect
    k_prep<<<DEG_BLKS + WSP_BLKS, 256>>>(W, (const unsigned int*)ei);
    // launch 1: decode + degree
    k_decode_deg<<<(N_EDGES + 255) / 256, 256>>>((const int*)ei);
    // launch 2: aggx self-loop init + dinv
    {
        long long total = (long long)N_NODES * 32;
        k_init_aggx_dinv<<<(int)((total + 255) / 256), 256>>>((const float4*)x);
    }
    // launch 3 (ncu samples this index): edge scatter
    {
        long long total = (long long)N_EDGES * 32;
        k_edge_scatter<<<(int)((total + 255) / 256), 256>>>((const float4*)x);
    }
    // launch 4: GEMM + bias + relu
    cudaFuncSetAttribute(k_gemm_relu,
                         cudaFuncAttributeMaxDynamicSharedMemorySize, SM_TOTAL);
    k_gemm_relu<<<NBLK, 256, SM_TOTAL>>>(b, out);
}

// round 7
// speedup vs baseline: 2.0695x; 1.0806x over previous
#include <cuda_runtime.h>
#include <cuda_bf16.h>
#include <cstdint>

#define N_NODES 100000
#define N_EDGES 600000
#define N_FEAT  128
#define NBLK    ((N_NODES + 127) / 128)   // 782

// Scratch (device globals). 16B alignment load-bearing for red.v4/int4 loads.
__device__ __align__(16) float g_deg[N_NODES];
__device__ __align__(16) float g_dinv[N_NODES];
__device__ __align__(16) float g_norm[N_EDGES];
__device__ __align__(16) float g_aggx[(size_t)N_NODES * N_FEAT];
__device__ __align__(16) int g_src[N_EDGES];
__device__ __align__(16) int g_dst[N_EDGES];
__device__ unsigned int g_or;   // dtype detection (0 => int64 layout)
// W split into bf16 hi/lo, m16n8k16 B-fragment order
__device__ __align__(16) uint2 g_wfragH[128 * 8 * 4];
__device__ __align__(16) uint2 g_wfragL[128 * 8 * 4];

// ---------------- prep: deg init + W split + dtype detect (one launch) ----
#define DEG_BLKS ((N_NODES + 255) / 256)          // 391
#define WSP_BLKS ((128 * 128 + 255) / 256)        // 64

__global__ void k_prep(const float* __restrict__ W,
                       const unsigned int* __restrict__ ew) {
    int bid = blockIdx.x, tid = threadIdx.x;
    if (bid < DEG_BLKS) {
        int i = bid * 256 + tid;
        if (i < N_NODES) g_deg[i] = 1.0f;          // self-loop pre-counted
        if (bid == 0) {
            __shared__ unsigned int s_or;
            if (tid == 0) s_or = 0u;
            __syncthreads();
            unsigned int v = 0u;
#pragma unroll
            for (int k = 0; k < 16; k++) {
                int e = (tid * 16 + k) * 146;      // <= 597,870 < N_EDGES
                v |= ew[2 * e + 1];
            }
#pragma unroll
            for (int s = 16; s > 0; s >>= 1)
                v |= __shfl_xor_sync(0xffffffffu, v, s);
            if ((tid & 31) == 0 && v) atomicOr(&s_or, v);
            __syncthreads();
            if (tid == 0) g_or = s_or;
        }
    } else {
        int i = (bid - DEG_BLKS) * 256 + tid;      // W split
        if (i < 128 * 128) {
            int k = i >> 7, n = i & 127;
            float v = W[i];
            __nv_bfloat16 h = __float2bfloat16_rn(v);
            __nv_bfloat16 l = __float2bfloat16_rn(v - __bfloat162float(h));
            int kstep = k >> 4, kk = k & 15;
            int t = (kk & 7) >> 1;
            int idx4 = (kk < 8) ? (kk & 1) : (2 + (kk & 1));
            int base = (n * 8 + kstep) * 4 + t;
            ((__nv_bfloat16*)g_wfragH)[base * 4 + idx4] = h;
            ((__nv_bfloat16*)g_wfragL)[base * 4 + idx4] = l;
        }
    }
}

// ---------------- decode + degree scatter ----------------
__global__ void k_decode_deg(const int* __restrict__ w) {
    int i = blockIdx.x * blockDim.x + threadIdx.x;
    if (i >= N_EDGES) return;
    int s, d;
    if (g_or == 0u) { s = w[2 * i]; d = w[2 * (N_EDGES + i)]; }
    else            { s = w[i];     d = w[N_EDGES + i]; }
    s = min(max(s, 0), N_NODES - 1);
    d = min(max(d, 0), N_NODES - 1);
    g_src[i] = s;
    g_dst[i] = d;
    atomicAdd(&g_deg[d], 1.0f);
}

// ---------------- init aggx = x * dinv^2, also writes g_dinv --------------
__global__ void k_init_aggx_dinv(const float4* __restrict__ x4) {
    int t = blockIdx.x * blockDim.x + threadIdx.x;  // N*32 threads
    if (t < N_NODES * 32) {
        int node = t >> 5;
        float di = rsqrtf(g_deg[node]);             // deg >= 1 always
        if ((t & 31) == 0) g_dinv[node] = di;
        float s = di * di;
        float4 v = x4[t];
        v.x *= s; v.y *= s; v.z *= s; v.w *= s;
        ((float4*)g_aggx)[t] = v;
    }
}

// ---------------- norm precompute: kills dependent gathers in scatter -----
__global__ void k_norm() {
    int i = blockIdx.x * blockDim.x + threadIdx.x;
    if (i < N_EDGES) g_norm[i] = g_dinv[g_src[i]] * g_dinv[g_dst[i]];
}

// ---------------- edge scatter: 4 edges/warp, MLP=4 -----------------------
__global__ void k_edge_scatter(const float4* __restrict__ x4) {
    int t = blockIdx.x * blockDim.x + threadIdx.x;
    int w = t >> 5;                  // warp id = edge quad id
    int e0 = w * 4;
    if (e0 >= N_EDGES) return;       // N_EDGES % 4 == 0
    int lane = t & 31;

    // 16B broadcast loads (all lanes same line)
    int4   s4 = *(const int4*)  &g_src[e0];
    int4   d4 = *(const int4*)  &g_dst[e0];
    float4 n4 = *(const float4*)&g_norm[e0];

    // 4 independent gathers in flight
    float4 v0 = x4[(size_t)s4.x * 32 + lane];
    float4 v1 = x4[(size_t)s4.y * 32 + lane];
    float4 v2 = x4[(size_t)s4.z * 32 + lane];
    float4 v3 = x4[(size_t)s4.w * 32 + lane];

    v0.x *= n4.x; v0.y *= n4.x; v0.z *= n4.x; v0.w *= n4.x;
    v1.x *= n4.y; v1.y *= n4.y; v1.z *= n4.y; v1.w *= n4.y;
    v2.x *= n4.z; v2.y *= n4.z; v2.z *= n4.z; v2.w *= n4.z;
    v3.x *= n4.w; v3.y *= n4.w; v3.z *= n4.w; v3.w *= n4.w;

    float* p0 = &g_aggx[(size_t)d4.x * N_FEAT + lane * 4];
    float* p1 = &g_aggx[(size_t)d4.y * N_FEAT + lane * 4];
    float* p2 = &g_aggx[(size_t)d4.z * N_FEAT + lane * 4];
    float* p3 = &g_aggx[(size_t)d4.w * N_FEAT + lane * 4];
    asm volatile("red.global.add.v4.f32 [%0], {%1,%2,%3,%4};"
                 :: "l"(p0), "f"(v0.x), "f"(v0.y), "f"(v0.z), "f"(v0.w) : "memory");
    asm volatile("red.global.add.v4.f32 [%0], {%1,%2,%3,%4};"
                 :: "l"(p1), "f"(v1.x), "f"(v1.y), "f"(v1.z), "f"(v1.w) : "memory");
    asm volatile("red.global.add.v4.f32 [%0], {%1,%2,%3,%4};"
                 :: "l"(p2), "f"(v2.x), "f"(v2.y), "f"(v2.z), "f"(v2.w) : "memory");
    asm volatile("red.global.add.v4.f32 [%0], {%1,%2,%3,%4};"
                 :: "l"(p3), "f"(v3.x), "f"(v3.y), "f"(v3.z), "f"(v3.w) : "memory");
}

// ---------------- GEMM: out = relu(aggx @ W + b) via bf16x3 mma ----------
#define MMA_BF16(d, a0, a1, a2, a3, b0, b1)                                 \
    asm volatile(                                                           \
        "mma.sync.aligned.m16n8k16.row.col.f32.bf16.bf16.f32 "              \
        "{%0,%1,%2,%3}, {%4,%5,%6,%7}, {%8,%9}, {%0,%1,%2,%3};"             \
        : "+f"(d[0]), "+f"(d[1]), "+f"(d[2]), "+f"(d[3])                    \
        : "r"(a0), "r"(a1), "r"(a2), "r"(a3), "r"(b0), "r"(b1))

#define SM_WFH 0
#define SM_WFL 32768
#define SM_AH  65536
#define SM_AL  (65536 + 33792)
#define SM_TOTAL (65536 + 2 * 33792)   // 133,120 B

__global__ void __launch_bounds__(256, 1)
k_gemm_relu(const float* __restrict__ b, float* __restrict__ out) {
    extern __shared__ char sm[];
    uint2* WfH = (uint2*)(sm + SM_WFH);
    uint2* WfL = (uint2*)(sm + SM_WFL);
    __nv_bfloat16* Ah = (__nv_bfloat16*)(sm + SM_AH);  // [128][132]
    __nv_bfloat16* Al = (__nv_bfloat16*)(sm + SM_AL);

    int tid = threadIdx.x;

#pragma unroll
    for (int i = 0; i < 16; i++) {
        WfH[tid + i * 256] = g_wfragH[tid + i * 256];
        WfL[tid + i * 256] = g_wfragL[tid + i * 256];
    }

    int rowbase = blockIdx.x * 128;
    const float4* A4 = (const float4*)g_aggx;
#pragma unroll
    for (int i = 0; i < 16; i++) {
        int idx = tid + i * 256;
        int r   = idx >> 5;
        int c4  = (idx & 31) * 4;
        int grow = min(rowbase + r, N_NODES - 1);
        float4 v = A4[(size_t)grow * 32 + (idx & 31)];
        float vs[4] = {v.x, v.y, v.z, v.w};
#pragma unroll
        for (int j = 0; j < 4; j++) {
            __nv_bfloat16 h = __float2bfloat16_rn(vs[j]);
            Ah[r * 132 + c4 + j] = h;
            Al[r * 132 + c4 + j] = __float2bfloat16_rn(vs[j] - __bfloat162float(h));
        }
    }
    __syncthreads();

    int warp = tid >> 5, lane = tid & 31;
    int g = lane >> 2, t = lane & 3;
    int r0 = warp * 16 + g, r1 = r0 + 8;

    float acc[16][4];
#pragma unroll
    for (int nt = 0; nt < 16; nt++)
#pragma unroll
        for (int j = 0; j < 4; j++) acc[nt][j] = 0.0f;

#pragma unroll
    for (int ks = 0; ks < 8; ks++) {
        int k0 = ks * 16;
        uint32_t ah0 = *(const uint32_t*)&Ah[r0 * 132 + k0 + 2 * t];
        uint32_t ah1 = *(const uint32_t*)&Ah[r1 * 132 + k0 + 2 * t];
        uint32_t ah2 = *(const uint32_t*)&Ah[r0 * 132 + k0 + 2 * t + 8];
        uint32_t ah3 = *(const uint32_t*)&Ah[r1 * 132 + k0 + 2 * t + 8];
        uint32_t al0 = *(const uint32_t*)&Al[r0 * 132 + k0 + 2 * t];
        uint32_t al1 = *(const uint32_t*)&Al[r1 * 132 + k0 + 2 * t];
        uint32_t al2 = *(const uint32_t*)&Al[r0 * 132 + k0 + 2 * t + 8];
        uint32_t al3 = *(const uint32_t*)&Al[r1 * 132 + k0 + 2 * t + 8];
#pragma unroll
        for (int nt = 0; nt < 16; nt++) {
            int n = nt * 8 + g;
            uint2 bh = WfH[(n * 8 + ks) * 4 + t];
            uint2 bl = WfL[(n * 8 + ks) * 4 + t];
            MMA_BF16(acc[nt], ah0, ah1, ah2, ah3, bh.x, bh.y);
            MMA_BF16(acc[nt], ah0, ah1, ah2, ah3, bl.x, bl.y);
            MMA_BF16(acc[nt], al0, al1, al2, al3, bh.x, bh.y);
        }
    }

    int growA = rowbase + warp * 16 + g;
#pragma unroll
    for (int nt = 0; nt < 16; nt++) {
        int c = nt * 8 + 2 * t;
        float2 bb = *(const float2*)&b[c];
        if (growA < N_NODES) {
            float2 o;
            o.x = fmaxf(acc[nt][0] + bb.x, 0.0f);
            o.y = fmaxf(acc[nt][1] + bb.y, 0.0f);
            *(float2*)&out[(size_t)growA * 128 + c] = o;
        }
        int grow1 = growA + 8;
        if (grow1 < N_NODES) {
            float2 o;
            o.x = fmaxf(acc[nt][2] + bb.x, 0.0f);
            o.y = fmaxf(acc[nt][3] + bb.y, 0.0f);
            *(float2*)&out[(size_t)grow1 * 128 + c] = o;
        }
    }
}

extern "C" void kernel_launch(void* const* d_in, const int* in_sizes, int n_in,
                              void* d_out, int out_size) {
    const float* x  = nullptr;
    const float* W  = nullptr;
    const float* b  = nullptr;
    const void*  ei = nullptr;
    for (int i = 0; i < n_in; i++) {
        switch (in_sizes[i]) {
            case 12800000: x  = (const float*)d_in[i]; break;
            case 16384:    W  = (const float*)d_in[i]; break;
            case 128:      b  = (const float*)d_in[i]; break;
            case 1200000:  ei = d_in[i];               break;
            default: break;
        }
    }
    float* out = (float*)d_out;
    (void)out_size;
    if (!x || !W || !b || !ei) return;

    // 0: deg init + W split + dtype detect
    k_prep<<<DEG_BLKS + WSP_BLKS, 256>>>(W, (const unsigned int*)ei);
    // 1: decode + degree
    k_decode_deg<<<(N_EDGES + 255) / 256, 256>>>((const int*)ei);
    // 2: aggx self-loop init + dinv
    {
        long long total = (long long)N_NODES * 32;
        k_init_aggx_dinv<<<(int)((total + 255) / 256), 256>>>((const float4*)x);
    }
    // 3: edge norms
    k_norm<<<(N_EDGES + 255) / 256, 256>>>();
    // 4: edge scatter (4 edges/warp)
    {
        long long total = (long long)(N_EDGES / 4) * 32;
        k_edge_scatter<<<(int)((total + 255) / 256), 256>>>((const float4*)x);
    }
    // 5: GEMM + bias + relu  (ncu -s 5 should land here)
    cudaFuncSetAttribute(k_gemm_relu,
                         cudaFuncAttributeMaxDynamicSharedMemorySize, SM_TOTAL);
    k_gemm_relu<<<NBLK, 256, SM_TOTAL>>>(b, out);
}

// round 8
// speedup vs baseline: 2.2777x; 1.1006x over previous
#include <cuda_runtime.h>
#include <cuda_bf16.h>
#include <cstdint>

#define N_NODES 100000
#define N_EDGES 600000
#define N_FEAT  128
#define NBLK    ((N_NODES + 127) / 128)   // 782

// Scratch (device globals). 16B alignment load-bearing for red.v4/int4 loads.
__device__ __align__(16) float g_deg[N_NODES];
__device__ __align__(16) float g_aggx[(size_t)N_NODES * N_FEAT];
__device__ __align__(16) int g_src[N_EDGES];
__device__ __align__(16) int g_dst[N_EDGES];
__device__ unsigned int g_or;   // dtype detection (0 => int64 layout)
// W split into bf16 hi/lo, m16n8k16 B-fragment order
__device__ __align__(16) uint2 g_wfragH[128 * 8 * 4];
__device__ __align__(16) uint2 g_wfragL[128 * 8 * 4];

// ---- prep: zero aggx + deg init + W split + dtype detect (one launch) ----
#define ZERO_BLKS ((N_NODES * 32 + 255) / 256)    // float4 units: 12,500
#define DEG_BLKS  ((N_NODES + 255) / 256)         // 391
#define WSP_BLKS  ((128 * 128 + 255) / 256)       // 64

__global__ void k_prep(const float* __restrict__ W,
                       const unsigned int* __restrict__ ew) {
    int bid = blockIdx.x, tid = threadIdx.x;
    if (bid < ZERO_BLKS) {
        int i = bid * 256 + tid;
        if (i < N_NODES * 32)
            ((float4*)g_aggx)[i] = make_float4(0.f, 0.f, 0.f, 0.f);
        return;
    }
    bid -= ZERO_BLKS;
    if (bid < DEG_BLKS) {
        int i = bid * 256 + tid;
        if (i < N_NODES) g_deg[i] = 1.0f;          // self-loop pre-counted
        if (bid == 0) {
            __shared__ unsigned int s_or;
            if (tid == 0) s_or = 0u;
            __syncthreads();
            unsigned int v = 0u;
#pragma unroll
            for (int k = 0; k < 16; k++) {
                int e = (tid * 16 + k) * 146;      // <= 597,870 < N_EDGES
                v |= ew[2 * e + 1];
            }
#pragma unroll
            for (int s = 16; s > 0; s >>= 1)
                v |= __shfl_xor_sync(0xffffffffu, v, s);
            if ((tid & 31) == 0 && v) atomicOr(&s_or, v);
            __syncthreads();
            if (tid == 0) g_or = s_or;
        }
    } else {
        int i = (bid - DEG_BLKS) * 256 + tid;      // W split
        if (i < 128 * 128) {
            int k = i >> 7, n = i & 127;
            float v = W[i];
            __nv_bfloat16 h = __float2bfloat16_rn(v);
            __nv_bfloat16 l = __float2bfloat16_rn(v - __bfloat162float(h));
            int kstep = k >> 4, kk = k & 15;
            int t = (kk & 7) >> 1;
            int idx4 = (kk < 8) ? (kk & 1) : (2 + (kk & 1));
            int base = (n * 8 + kstep) * 4 + t;
            ((__nv_bfloat16*)g_wfragH)[base * 4 + idx4] = h;
            ((__nv_bfloat16*)g_wfragL)[base * 4 + idx4] = l;
        }
    }
}

// ---------------- decode + degree scatter ----------------
__global__ void k_decode_deg(const int* __restrict__ w) {
    int i = blockIdx.x * blockDim.x + threadIdx.x;
    if (i >= N_EDGES) return;
    int s, d;
    if (g_or == 0u) { s = w[2 * i]; d = w[2 * (N_EDGES + i)]; }
    else            { s = w[i];     d = w[N_EDGES + i]; }
    s = min(max(s, 0), N_NODES - 1);
    d = min(max(d, 0), N_NODES - 1);
    g_src[i] = s;
    g_dst[i] = d;
    atomicAdd(&g_deg[d], 1.0f);
}

// ------- edge scatter: 4 edges/warp, on-the-fly norm, MLP=12 -------
__global__ void k_edge_scatter(const float4* __restrict__ x4) {
    int t = blockIdx.x * blockDim.x + threadIdx.x;
    int w = t >> 5;                  // warp id = edge quad id
    int e0 = w * 4;
    if (e0 >= N_EDGES) return;       // N_EDGES % 4 == 0
    int lane = t & 31;

    // 16B broadcast loads (all lanes same line)
    int4 s4 = *(const int4*)&g_src[e0];
    int4 d4 = *(const int4*)&g_dst[e0];

    // lanes 0-3: dinv[src[i]], lanes 4-7: dinv[dst[i]] (independent gathers)
    int nid;
    {
        int l = lane & 7;
        const int* sp = (const int*)&s4;
        const int* dp = (const int*)&d4;
        nid = (lane < 4) ? sp[l] : dp[l - 4];
    }
    float dv = 0.0f;
    if (lane < 8) dv = rsqrtf(g_deg[nid]);

    // 4 independent x-row gathers in flight (overlap the deg gathers)
    float4 v0 = x4[(size_t)s4.x * 32 + lane];
    float4 v1 = x4[(size_t)s4.y * 32 + lane];
    float4 v2 = x4[(size_t)s4.z * 32 + lane];
    float4 v3 = x4[(size_t)s4.w * 32 + lane];

    float n0 = __shfl_sync(0xffffffffu, dv, 0) * __shfl_sync(0xffffffffu, dv, 4);
    float n1 = __shfl_sync(0xffffffffu, dv, 1) * __shfl_sync(0xffffffffu, dv, 5);
    float n2 = __shfl_sync(0xffffffffu, dv, 2) * __shfl_sync(0xffffffffu, dv, 6);
    float n3 = __shfl_sync(0xffffffffu, dv, 3) * __shfl_sync(0xffffffffu, dv, 7);

    v0.x *= n0; v0.y *= n0; v0.z *= n0; v0.w *= n0;
    v1.x *= n1; v1.y *= n1; v1.z *= n1; v1.w *= n1;
    v2.x *= n2; v2.y *= n2; v2.z *= n2; v2.w *= n2;
    v3.x *= n3; v3.y *= n3; v3.z *= n3; v3.w *= n3;

    float* p0 = &g_aggx[(size_t)d4.x * N_FEAT + lane * 4];
    float* p1 = &g_aggx[(size_t)d4.y * N_FEAT + lane * 4];
    float* p2 = &g_aggx[(size_t)d4.z * N_FEAT + lane * 4];
    float* p3 = &g_aggx[(size_t)d4.w * N_FEAT + lane * 4];
    asm volatile("red.global.add.v4.f32 [%0], {%1,%2,%3,%4};"
                 :: "l"(p0), "f"(v0.x), "f"(v0.y), "f"(v0.z), "f"(v0.w) : "memory");
    asm volatile("red.global.add.v4.f32 [%0], {%1,%2,%3,%4};"
                 :: "l"(p1), "f"(v1.x), "f"(v1.y), "f"(v1.z), "f"(v1.w) : "memory");
    asm volatile("red.global.add.v4.f32 [%0], {%1,%2,%3,%4};"
                 :: "l"(p2), "f"(v2.x), "f"(v2.y), "f"(v2.z), "f"(v2.w) : "memory");
    asm volatile("red.global.add.v4.f32 [%0], {%1,%2,%3,%4};"
                 :: "l"(p3), "f"(v3.x), "f"(v3.y), "f"(v3.z), "f"(v3.w) : "memory");
}

// --- GEMM: out = relu((aggx + x*dinv^2) @ W + b) via bf16x3 mma ---
#define MMA_BF16(d, a0, a1, a2, a3, b0, b1)                                 \
    asm volatile(                                                           \
        "mma.sync.aligned.m16n8k16.row.col.f32.bf16.bf16.f32 "              \
        "{%0,%1,%2,%3}, {%4,%5,%6,%7}, {%8,%9}, {%0,%1,%2,%3};"             \
        : "+f"(d[0]), "+f"(d[1]), "+f"(d[2]), "+f"(d[3])                    \
        : "r"(a0), "r"(a1), "r"(a2), "r"(a3), "r"(b0), "r"(b1))

// smem: WfH [0,32768) | Ah [32768,+33792) | Al (+33792)  = 100,352 B
#define SM_WFH 0
#define SM_AH  32768
#define SM_AL  (32768 + 33792)
#define SM_TOTAL (32768 + 2 * 33792)

__global__ void __launch_bounds__(256, 2)
k_gemm_relu(const float4* __restrict__ x4, const float* __restrict__ b,
            float* __restrict__ out) {
    extern __shared__ char sm[];
    uint2* WfH = (uint2*)(sm + SM_WFH);
    __nv_bfloat16* Ah = (__nv_bfloat16*)(sm + SM_AH);  // [128][132]
    __nv_bfloat16* Al = (__nv_bfloat16*)(sm + SM_AL);

    int tid = threadIdx.x;

#pragma unroll
    for (int i = 0; i < 16; i++) WfH[tid + i * 256] = g_wfragH[tid + i * 256];

    int rowbase = blockIdx.x * 128;
    const float4* A4 = (const float4*)g_aggx;
#pragma unroll
    for (int i = 0; i < 16; i++) {
        int idx = tid + i * 256;
        int r   = idx >> 5;
        int c   = idx & 31;
        int grow = min(rowbase + r, N_NODES - 1);
        float di = rsqrtf(g_deg[grow]);
        float s2 = di * di;
        float4 va = A4[(size_t)grow * 32 + c];
        float4 vx = x4[(size_t)grow * 32 + c];
        va.x += vx.x * s2; va.y += vx.y * s2;
        va.z += vx.z * s2; va.w += vx.w * s2;
        float vs[4] = {va.x, va.y, va.z, va.w};
        int c4 = c * 4;
#pragma unroll
        for (int j = 0; j < 4; j++) {
            __nv_bfloat16 h = __float2bfloat16_rn(vs[j]);
            Ah[r * 132 + c4 + j] = h;
            Al[r * 132 + c4 + j] = __float2bfloat16_rn(vs[j] - __bfloat162float(h));
        }
    }
    __syncthreads();

    int warp = tid >> 5, lane = tid & 31;
    int g = lane >> 2, t = lane & 3;
    int r0 = warp * 16 + g, r1 = r0 + 8;

    float acc[16][4];
#pragma unroll
    for (int nt = 0; nt < 16; nt++)
#pragma unroll
        for (int j = 0; j < 4; j++) acc[nt][j] = 0.0f;

#pragma unroll
    for (int ks = 0; ks < 8; ks++) {
        int k0 = ks * 16;
        uint32_t ah0 = *(const uint32_t*)&Ah[r0 * 132 + k0 + 2 * t];
        uint32_t ah1 = *(const uint32_t*)&Ah[r1 * 132 + k0 + 2 * t];
        uint32_t ah2 = *(const uint32_t*)&Ah[r0 * 132 + k0 + 2 * t + 8];
        uint32_t ah3 = *(const uint32_t*)&Ah[r1 * 132 + k0 + 2 * t + 8];
        uint32_t al0 = *(const uint32_t*)&Al[r0 * 132 + k0 + 2 * t];
        uint32_t al1 = *(const uint32_t*)&Al[r1 * 132 + k0 + 2 * t];
        uint32_t al2 = *(const uint32_t*)&Al[r0 * 132 + k0 + 2 * t + 8];
        uint32_t al3 = *(const uint32_t*)&Al[r1 * 132 + k0 + 2 * t + 8];
#pragma unroll
        for (int nt = 0; nt < 16; nt++) {
            int n = nt * 8 + g;
            uint2 bh = WfH[(n * 8 + ks) * 4 + t];
            uint2 bl = g_wfragL[(n * 8 + ks) * 4 + t];   // L1-resident
            MMA_BF16(acc[nt], ah0, ah1, ah2, ah3, bh.x, bh.y);
            MMA_BF16(acc[nt], ah0, ah1, ah2, ah3, bl.x, bl.y);
            MMA_BF16(acc[nt], al0, al1, al2, al3, bh.x, bh.y);
        }
    }

    int growA = rowbase + warp * 16 + g;
#pragma unroll
    for (int nt = 0; nt < 16; nt++) {
        int c = nt * 8 + 2 * t;
        float2 bb = *(const float2*)&b[c];
        if (growA < N_NODES) {
            float2 o;
            o.x = fmaxf(acc[nt][0] + bb.x, 0.0f);
            o.y = fmaxf(acc[nt][1] + bb.y, 0.0f);
            *(float2*)&out[(size_t)growA * 128 + c] = o;
        }
        int grow1 = growA + 8;
        if (grow1 < N_NODES) {
            float2 o;
            o.x = fmaxf(acc[nt][2] + bb.x, 0.0f);
            o.y = fmaxf(acc[nt][3] + bb.y, 0.0f);
            *(float2*)&out[(size_t)grow1 * 128 + c] = o;
        }
    }
}

extern "C" void kernel_launch(void* const* d_in, const int* in_sizes, int n_in,
                              void* d_out, int out_size) {
    const float* x  = nullptr;
    const float* W  = nullptr;
    const float* b  = nullptr;
    const void*  ei = nullptr;
    for (int i = 0; i < n_in; i++) {
        switch (in_sizes[i]) {
            case 12800000: x  = (const float*)d_in[i]; break;
            case 16384:    W  = (const float*)d_in[i]; break;
            case 128:      b  = (const float*)d_in[i]; break;
            case 1200000:  ei = d_in[i];               break;
            default: break;
        }
    }
    float* out = (float*)d_out;
    (void)out_size;
    if (!x || !W || !b || !ei) return;

    // 0: zero aggx + deg init + W split + dtype detect
    k_prep<<<ZERO_BLKS + DEG_BLKS + WSP_BLKS, 256>>>(W, (const unsigned int*)ei);
    // 1: decode + degree
    k_decode_deg<<<(N_EDGES + 255) / 256, 256>>>((const int*)ei);
    // 2: edge scatter (4 edges/warp, fused norm)
    {
        long long total = (long long)(N_EDGES / 4) * 32;
        k_edge_scatter<<<(int)((total + 255) / 256), 256>>>((const float4*)x);
    }
    // 3: GEMM + self-loop + bias + relu   (ncu samples index 3)
    cudaFuncSetAttribute(k_gemm_relu,
                         cudaFuncAttributeMaxDynamicSharedMemorySize, SM_TOTAL);
    k_gemm_relu<<<NBLK, 256, SM_TOTAL>>>((const float4*)x, b, out);
}

// round 9
// speedup vs baseline: 2.3719x; 1.0414x over previous
#include <cuda_runtime.h>
#include <cuda_bf16.h>
#include <cstdint>

#define N_NODES 100000
#define N_EDGES 600000
#define N_FEAT  128
#define TILE_M  64
#define NBLK2   ((N_NODES + TILE_M - 1) / TILE_M)   // 1563

// Scratch (device globals). 16B alignment load-bearing for red.v4/int4 loads.
__device__ __align__(16) float g_deg[N_NODES];
__device__ __align__(16) float g_aggx[(size_t)N_NODES * N_FEAT];
__device__ __align__(16) int g_src[N_EDGES];
__device__ __align__(16) int g_dst[N_EDGES];
__device__ unsigned int g_or;   // dtype detection (0 => int64 layout)
// W split into bf16 hi/lo, m16n8k16 B-fragment order
__device__ __align__(16) uint2 g_wfragH[128 * 8 * 4];
__device__ __align__(16) uint2 g_wfragL[128 * 8 * 4];

// ---- prep: zero aggx + deg init + W split + dtype detect (one launch) ----
#define ZERO_BLKS ((N_NODES * 32 + 255) / 256)    // float4 units: 12,500
#define DEG_BLKS  ((N_NODES + 255) / 256)         // 391
#define WSP_BLKS  ((128 * 128 + 255) / 256)       // 64

__global__ void k_prep(const float* __restrict__ W,
                       const unsigned int* __restrict__ ew) {
    int bid = blockIdx.x, tid = threadIdx.x;
    if (bid < ZERO_BLKS) {
        int i = bid * 256 + tid;
        if (i < N_NODES * 32)
            ((float4*)g_aggx)[i] = make_float4(0.f, 0.f, 0.f, 0.f);
        return;
    }
    bid -= ZERO_BLKS;
    if (bid < DEG_BLKS) {
        int i = bid * 256 + tid;
        if (i < N_NODES) g_deg[i] = 1.0f;          // self-loop pre-counted
        if (bid == 0) {
            __shared__ unsigned int s_or;
            if (tid == 0) s_or = 0u;
            __syncthreads();
            unsigned int v = 0u;
#pragma unroll
            for (int k = 0; k < 16; k++) {
                int e = (tid * 16 + k) * 146;      // <= 597,870 < N_EDGES
                v |= ew[2 * e + 1];
            }
#pragma unroll
            for (int s = 16; s > 0; s >>= 1)
                v |= __shfl_xor_sync(0xffffffffu, v, s);
            if ((tid & 31) == 0 && v) atomicOr(&s_or, v);
            __syncthreads();
            if (tid == 0) g_or = s_or;
        }
    } else {
        int i = (bid - DEG_BLKS) * 256 + tid;      // W split
        if (i < 128 * 128) {
            int k = i >> 7, n = i & 127;
            float v = W[i];
            __nv_bfloat16 h = __float2bfloat16_rn(v);
            __nv_bfloat16 l = __float2bfloat16_rn(v - __bfloat162float(h));
            int kstep = k >> 4, kk = k & 15;
            int t = (kk & 7) >> 1;
            int idx4 = (kk < 8) ? (kk & 1) : (2 + (kk & 1));
            int base = (n * 8 + kstep) * 4 + t;
            ((__nv_bfloat16*)g_wfragH)[base * 4 + idx4] = h;
            ((__nv_bfloat16*)g_wfragL)[base * 4 + idx4] = l;
        }
    }
}

// ---------------- decode + degree scatter ----------------
__global__ void k_decode_deg(const int* __restrict__ w) {
    int i = blockIdx.x * blockDim.x + threadIdx.x;
    if (i >= N_EDGES) return;
    int s, d;
    if (g_or == 0u) { s = w[2 * i]; d = w[2 * (N_EDGES + i)]; }
    else            { s = w[i];     d = w[N_EDGES + i]; }
    s = min(max(s, 0), N_NODES - 1);
    d = min(max(d, 0), N_NODES - 1);
    g_src[i] = s;
    g_dst[i] = d;
    atomicAdd(&g_deg[d], 1.0f);
}

// ------- edge scatter: 4 edges/warp, on-the-fly norm, MLP=12 -------
__global__ void k_edge_scatter(const float4* __restrict__ x4) {
    int t = blockIdx.x * blockDim.x + threadIdx.x;
    int w = t >> 5;                  // warp id = edge quad id
    int e0 = w * 4;
    if (e0 >= N_EDGES) return;       // N_EDGES % 4 == 0
    int lane = t & 31;

    int4 s4 = *(const int4*)&g_src[e0];
    int4 d4 = *(const int4*)&g_dst[e0];

    int nid;
    {
        int l = lane & 7;
        const int* sp = (const int*)&s4;
        const int* dp = (const int*)&d4;
        nid = (lane < 4) ? sp[l] : dp[l - 4];
    }
    float dv = 0.0f;
    if (lane < 8) dv = rsqrtf(g_deg[nid]);

    float4 v0 = x4[(size_t)s4.x * 32 + lane];
    float4 v1 = x4[(size_t)s4.y * 32 + lane];
    float4 v2 = x4[(size_t)s4.z * 32 + lane];
    float4 v3 = x4[(size_t)s4.w * 32 + lane];

    float n0 = __shfl_sync(0xffffffffu, dv, 0) * __shfl_sync(0xffffffffu, dv, 4);
    float n1 = __shfl_sync(0xffffffffu, dv, 1) * __shfl_sync(0xffffffffu, dv, 5);
    float n2 = __shfl_sync(0xffffffffu, dv, 2) * __shfl_sync(0xffffffffu, dv, 6);
    float n3 = __shfl_sync(0xffffffffu, dv, 3) * __shfl_sync(0xffffffffu, dv, 7);

    v0.x *= n0; v0.y *= n0; v0.z *= n0; v0.w *= n0;
    v1.x *= n1; v1.y *= n1; v1.z *= n1; v1.w *= n1;
    v2.x *= n2; v2.y *= n2; v2.z *= n2; v2.w *= n2;
    v3.x *= n3; v3.y *= n3; v3.z *= n3; v3.w *= n3;

    float* p0 = &g_aggx[(size_t)d4.x * N_FEAT + lane * 4];
    float* p1 = &g_aggx[(size_t)d4.y * N_FEAT + lane * 4];
    float* p2 = &g_aggx[(size_t)d4.z * N_FEAT + lane * 4];
    float* p3 = &g_aggx[(size_t)d4.w * N_FEAT + lane * 4];
    asm volatile("red.global.add.v4.f32 [%0], {%1,%2,%3,%4};"
                 :: "l"(p0), "f"(v0.x), "f"(v0.y), "f"(v0.z), "f"(v0.w) : "memory");
    asm volatile("red.global.add.v4.f32 [%0], {%1,%2,%3,%4};"
                 :: "l"(p1), "f"(v1.x), "f"(v1.y), "f"(v1.z), "f"(v1.w) : "memory");
    asm volatile("red.global.add.v4.f32 [%0], {%1,%2,%3,%4};"
                 :: "l"(p2), "f"(v2.x), "f"(v2.y), "f"(v2.z), "f"(v2.w) : "memory");
    asm volatile("red.global.add.v4.f32 [%0], {%1,%2,%3,%4};"
                 :: "l"(p3), "f"(v3.x), "f"(v3.y), "f"(v3.z), "f"(v3.w) : "memory");
}

// --- GEMM: out = relu((aggx + x*dinv^2) @ W + b), 64-row tiles, occ=3 ---
#define MMA_BF16(d, a0, a1, a2, a3, b0, b1)                                 \
    asm volatile(                                                           \
        "mma.sync.aligned.m16n8k16.row.col.f32.bf16.bf16.f32 "              \
        "{%0,%1,%2,%3}, {%4,%5,%6,%7}, {%8,%9}, {%0,%1,%2,%3};"             \
        : "+f"(d[0]), "+f"(d[1]), "+f"(d[2]), "+f"(d[3])                    \
        : "r"(a0), "r"(a1), "r"(a2), "r"(a3), "r"(b0), "r"(b1))

// smem: WfH [0,32768) | Ah [32768,+16896) | Al (+16896)  = 66,560 B
#define SM_WFH 0
#define SM_AH  32768
#define SM_AL  (32768 + 16896)
#define SM_TOTAL (32768 + 2 * 16896)

__global__ void __launch_bounds__(256, 3)
k_gemm_relu(const float4* __restrict__ x4, const float* __restrict__ b,
            float* __restrict__ out) {
    extern __shared__ char sm[];
    uint2* WfH = (uint2*)(sm + SM_WFH);
    __nv_bfloat16* Ah = (__nv_bfloat16*)(sm + SM_AH);  // [64][132]
    __nv_bfloat16* Al = (__nv_bfloat16*)(sm + SM_AL);

    int tid = threadIdx.x;

#pragma unroll
    for (int i = 0; i < 16; i++) WfH[tid + i * 256] = g_wfragH[tid + i * 256];

    int rowbase = blockIdx.x * TILE_M;
    const float4* A4 = (const float4*)g_aggx;
#pragma unroll
    for (int i = 0; i < 8; i++) {                 // 64 rows x 32 float4
        int idx = tid + i * 256;
        int r   = idx >> 5;
        int c   = idx & 31;
        int grow = min(rowbase + r, N_NODES - 1);
        float di = rsqrtf(g_deg[grow]);
        float s2 = di * di;
        float4 va = A4[(size_t)grow * 32 + c];
        float4 vx = x4[(size_t)grow * 32 + c];
        va.x += vx.x * s2; va.y += vx.y * s2;
        va.z += vx.z * s2; va.w += vx.w * s2;
        float vs[4] = {va.x, va.y, va.z, va.w};
        int c4 = c * 4;
#pragma unroll
        for (int j = 0; j < 4; j++) {
            __nv_bfloat16 h = __float2bfloat16_rn(vs[j]);
            Ah[r * 132 + c4 + j] = h;
            Al[r * 132 + c4 + j] = __float2bfloat16_rn(vs[j] - __bfloat162float(h));
        }
    }
    __syncthreads();

    // 8 warps = 4 row-groups (16 rows) x 2 N-halves (64 cols)
    int warp = tid >> 5, lane = tid & 31;
    int rg = warp & 3, nh = warp >> 2;
    int g = lane >> 2, t = lane & 3;
    int r0 = rg * 16 + g, r1 = r0 + 8;

    float acc[8][4];
#pragma unroll
    for (int nt = 0; nt < 8; nt++)
#pragma unroll
        for (int j = 0; j < 4; j++) acc[nt][j] = 0.0f;

#pragma unroll
    for (int ks = 0; ks < 8; ks++) {
        int k0 = ks * 16;
        uint32_t ah0 = *(const uint32_t*)&Ah[r0 * 132 + k0 + 2 * t];
        uint32_t ah1 = *(const uint32_t*)&Ah[r1 * 132 + k0 + 2 * t];
        uint32_t ah2 = *(const uint32_t*)&Ah[r0 * 132 + k0 + 2 * t + 8];
        uint32_t ah3 = *(const uint32_t*)&Ah[r1 * 132 + k0 + 2 * t + 8];
        uint32_t al0 = *(const uint32_t*)&Al[r0 * 132 + k0 + 2 * t];
        uint32_t al1 = *(const uint32_t*)&Al[r1 * 132 + k0 + 2 * t];
        uint32_t al2 = *(const uint32_t*)&Al[r0 * 132 + k0 + 2 * t + 8];
        uint32_t al3 = *(const uint32_t*)&Al[r1 * 132 + k0 + 2 * t + 8];
#pragma unroll
        for (int nt = 0; nt < 8; nt++) {
            int n = nh * 64 + nt * 8 + g;
            uint2 bh = WfH[(n * 8 + ks) * 4 + t];
            uint2 bl = g_wfragL[(n * 8 + ks) * 4 + t];   // L1-resident
            MMA_BF16(acc[nt], ah0, ah1, ah2, ah3, bh.x, bh.y);
            MMA_BF16(acc[nt], ah0, ah1, ah2, ah3, bl.x, bl.y);
            MMA_BF16(acc[nt], al0, al1, al2, al3, bh.x, bh.y);
        }
    }

    int growA = rowbase + rg * 16 + g;
#pragma unroll
    for (int nt = 0; nt < 8; nt++) {
        int c = nh * 64 + nt * 8 + 2 * t;
        float2 bb = *(const float2*)&b[c];
        if (growA < N_NODES) {
            float2 o;
            o.x = fmaxf(acc[nt][0] + bb.x, 0.0f);
            o.y = fmaxf(acc[nt][1] + bb.y, 0.0f);
            *(float2*)&out[(size_t)growA * 128 + c] = o;
        }
        int grow1 = growA + 8;
        if (grow1 < N_NODES) {
            float2 o;
            o.x = fmaxf(acc[nt][2] + bb.x, 0.0f);
            o.y = fmaxf(acc[nt][3] + bb.y, 0.0f);
            *(float2*)&out[(size_t)grow1 * 128 + c] = o;
        }
    }
}

extern "C" void kernel_launch(void* const* d_in, const int* in_sizes, int n_in,
                              void* d_out, int out_size) {
    const float* x  = nullptr;
    const float* W  = nullptr;
    const float* b  = nullptr;
    const void*  ei = nullptr;
    for (int i = 0; i < n_in; i++) {
        switch (in_sizes[i]) {
            case 12800000: x  = (const float*)d_in[i]; break;
            case 16384:    W  = (const float*)d_in[i]; break;
            case 128:      b  = (const float*)d_in[i]; break;
            case 1200000:  ei = d_in[i];               break;
            default: break;
        }
    }
    float* out = (float*)d_out;
    (void)out_size;
    if (!x || !W || !b || !ei) return;

    // 0: zero aggx + deg init + W split + dtype detect
    k_prep<<<ZERO_BLKS + DEG_BLKS + WSP_BLKS, 256>>>(W, (const unsigned int*)ei);
    // 1: decode + degree
    k_decode_deg<<<(N_EDGES + 255) / 256, 256>>>((const int*)ei);
    // 2: edge scatter (4 edges/warp, fused norm)
    {
        long long total = (long long)(N_EDGES / 4) * 32;
        k_edge_scatter<<<(int)((total + 255) / 256), 256>>>((const float4*)x);
    }
    // 3: GEMM + self-loop + bias + relu   (ncu samples index 3)
    cudaFuncSetAttribute(k_gemm_relu,
                         cudaFuncAttributeMaxDynamicSharedMemorySize, SM_TOTAL);
    k_gemm_relu<<<NBLK2, 256, SM_TOTAL>>>((const float4*)x, b, out);
}